// round 14
// baseline (speedup 1.0000x reference)
#include <cuda_runtime.h>
#include <cuda_bf16.h>
#include <cstdint>

#define NN 8192
#define FIN 512
#define FOUT 64
#define JW 4096       // cols per CTA (j halves)
#define NT (JW / 64)  // 64 tiles

// ---------------- scratch globals (no allocations allowed) ----------------
__device__ float g_h[NN * FOUT];
__device__ float g_ssrc[NN];
__device__ float g_G[NN];                    // exp(0.8 * s_src)
__device__ float4 g_colf[NN];                // {F=exp(sd), F02=exp(0.2 sd), sd, 0}
__device__ __nv_bfloat16 g_HThi[FOUT * NN];  // H^T high bf16, [f][i]
__device__ __nv_bfloat16 g_HTlo[FOUT * NN];  // H^T residual bf16
__device__ float g_part[2 * NN * FOUT];      // partial numerators per j-half
__device__ float g_psum[2 * NN];             // partial row sums per j-half

__device__ __forceinline__ uint32_t smem_u32(const void* p) {
    uint32_t a;
    asm("{ .reg .u64 t; cvta.to.shared.u64 t, %1; cvt.u32.u64 %0, t; }" : "=r"(a) : "l"(p));
    return a;
}
__device__ __forceinline__ void ldsm4(uint32_t* r, uint32_t addr) {
    asm volatile("ldmatrix.sync.aligned.m8n8.x4.shared.b16 {%0,%1,%2,%3}, [%4];"
                 : "=r"(r[0]), "=r"(r[1]), "=r"(r[2]), "=r"(r[3]) : "r"(addr));
}
__device__ __forceinline__ void mma_bf16(float* c, const uint32_t* a, uint32_t b0, uint32_t b1) {
    asm volatile(
        "mma.sync.aligned.m16n8k16.row.col.f32.bf16.bf16.f32 "
        "{%0,%1,%2,%3}, {%4,%5,%6,%7}, {%8,%9}, {%0,%1,%2,%3};"
        : "+f"(c[0]), "+f"(c[1]), "+f"(c[2]), "+f"(c[3])
        : "r"(a[0]), "r"(a[1]), "r"(a[2]), "r"(a[3]), "r"(b0), "r"(b1));
}
__device__ __forceinline__ void mbar_init(uint32_t a, uint32_t c) {
    asm volatile("mbarrier.init.shared.b64 [%0], %1;" :: "r"(a), "r"(c) : "memory");
}
__device__ __forceinline__ void mbar_expect(uint32_t a, uint32_t tx) {
    asm volatile("mbarrier.arrive.expect_tx.shared.b64 _, [%0], %1;" :: "r"(a), "r"(tx) : "memory");
}
__device__ __forceinline__ void mbar_wait(uint32_t a, uint32_t par) {
    asm volatile(
        "{\n\t.reg .pred P1;\n\t"
        "WL_%=:\n\t"
        "mbarrier.try_wait.parity.acquire.cta.shared::cta.b64 P1, [%0], %1, 0x989680;\n\t"
        "@P1 bra.uni WD_%=;\n\t"
        "bra.uni WL_%=;\n\t"
        "WD_%=:\n\t}"
        :: "r"(a), "r"(par) : "memory");
}
__device__ __forceinline__ void bulk_g2s(uint32_t dst, const void* src, uint32_t bytes, uint32_t mbar) {
    asm volatile(
        "cp.async.bulk.shared::cta.global.mbarrier::complete_tx::bytes [%0], [%1], %2, [%3];"
        :: "r"(dst), "l"(src), "r"(bytes), "r"(mbar) : "memory");
}
__device__ __forceinline__ void bar_sync(int id, int cnt) {
    asm volatile("bar.sync %0, %1;" :: "r"(id), "r"(cnt) : "memory");
}
__device__ __forceinline__ void bar_arrive(int id, int cnt) {
    asm volatile("bar.arrive %0, %1;" :: "r"(id), "r"(cnt) : "memory");
}

// ---------------- Kernel A: h = X @ W ----------------
__global__ __launch_bounds__(256) void k_gemm_h(const float* __restrict__ X,
                                                const float* __restrict__ W,
                                                float* __restrict__ H) {
    __shared__ float sA[32][65];
    __shared__ float sB[32][68];
    int t = threadIdx.x;
    int m0 = blockIdx.x * 64;
    int tr = t >> 4, tc = t & 15;
    float acc[4][4];
#pragma unroll
    for (int i = 0; i < 4; i++)
#pragma unroll
        for (int j = 0; j < 4; j++) acc[i][j] = 0.f;

    float rA[8], rB[8];
#pragma unroll
    for (int u = 0; u < 8; u++) {
        int g = u * 256 + t;
        int m = g >> 5, k = g & 31;
        rA[u] = X[(m0 + m) * FIN + k];
    }
#pragma unroll
    for (int u = 0; u < 8; u++) {
        int g = u * 256 + t;
        int k = g >> 6, n = g & 63;
        rB[u] = W[k * FOUT + n];
    }

    for (int kc = 0; kc < 16; kc++) {
        __syncthreads();
#pragma unroll
        for (int u = 0; u < 8; u++) {
            int g = u * 256 + t;
            int m = g >> 5, k = g & 31;
            sA[k][m] = rA[u];
        }
#pragma unroll
        for (int u = 0; u < 8; u++) {
            int g = u * 256 + t;
            int k = g >> 6, n = g & 63;
            sB[k][n] = rB[u];
        }
        __syncthreads();
        if (kc + 1 < 16) {
            int k0 = (kc + 1) * 32;
#pragma unroll
            for (int u = 0; u < 8; u++) {
                int g = u * 256 + t;
                int m = g >> 5, k = g & 31;
                rA[u] = X[(m0 + m) * FIN + k0 + k];
            }
#pragma unroll
            for (int u = 0; u < 8; u++) {
                int g = u * 256 + t;
                int k = g >> 6, n = g & 63;
                rB[u] = W[(k0 + k) * FOUT + n];
            }
        }
#pragma unroll
        for (int k = 0; k < 32; k++) {
            float a[4], b[4];
#pragma unroll
            for (int i = 0; i < 4; i++) a[i] = sA[k][tr + 16 * i];
#pragma unroll
            for (int j = 0; j < 4; j++) b[j] = sB[k][tc + 16 * j];
#pragma unroll
            for (int i = 0; i < 4; i++)
#pragma unroll
                for (int j = 0; j < 4; j++) acc[i][j] += a[i] * b[j];
        }
    }
#pragma unroll
    for (int i = 0; i < 4; i++)
#pragma unroll
        for (int j = 0; j < 4; j++)
            H[(m0 + tr + 16 * i) * FOUT + tc + 16 * j] = acc[i][j];
}

// ---------------- Kernel A2: scores + exp factors ----------------
__global__ __launch_bounds__(256) void k_scores(const float* __restrict__ H,
                                                const float* __restrict__ a) {
    int i = blockIdx.x * blockDim.x + threadIdx.x;
    const float4* hr = (const float4*)(H + i * FOUT);
    const float4* av = (const float4*)a;
    float ss = 0.f, sd = 0.f;
#pragma unroll
    for (int f = 0; f < 16; f++) {
        float4 h = hr[f];
        float4 as = av[f];
        float4 ad = av[16 + f];
        ss += h.x * as.x + h.y * as.y + h.z * as.z + h.w * as.w;
        sd += h.x * ad.x + h.y * ad.y + h.z * ad.z + h.w * ad.w;
    }
    g_ssrc[i] = ss;
    g_G[i] = expf(0.8f * ss);
    g_colf[i] = make_float4(expf(sd), expf(0.2f * sd), sd, 0.f);
}

// ---------------- Kernel A3: transpose H -> HT hi/lo bf16 ----------------
__global__ __launch_bounds__(256) void k_transpose() {
    __shared__ float tile[64][65];
    int t = threadIdx.x;
    int i0 = blockIdx.x * 64;
#pragma unroll
    for (int u = 0; u < 16; u++) {
        int idx = u * 256 + t;
        int r = idx >> 6, c = idx & 63;
        tile[r][c] = g_h[(i0 + r) * FOUT + c];
    }
    __syncthreads();
#pragma unroll
    for (int u = 0; u < 16; u++) {
        int idx = u * 256 + t;
        int f = idx >> 6, i = idx & 63;
        float v = tile[i][f];
        __nv_bfloat16 hb = __float2bfloat16(v);
        float hv = __bfloat162float(hb);
        __nv_bfloat16 lb = __float2bfloat16(v - hv);
        g_HThi[f * NN + i0 + i] = hb;
        g_HTlo[f * NN + i0 + i] = lb;
    }
}

// ---------------- Kernel B: warp-specialized HMMA attention ----------------
// smem (u32 offsets):
//   P[b]: hi at b*9216, lo at b*9216+4608   (128 rows x 36, BK=64)
//   B[b]: 18432 + b*4608; hi +0, lo +2304   (64 rows x 36)
//   adj[b]: 27648 + b*8704 (128 rows x 68)
//   colf[b]: 45056 + b*256 (64 float4)
//   mbars: 45568 (A0,A1,B0,B1)
#define SPS 36
#define SAS 68
#define PBUF 9216
#define PLO 4608
#define B_OFF 18432
#define BBUF 4608
#define BLO 2304
#define ADJ_OFF 27648
#define ABUF 8704
#define CF_OFF 45056
#define MB_OFF 45568
#define SMEM_U32 45576  // 182304 bytes

#define ADJ_TX (128u * 256u + 1024u)
#define B_TX (128u * 128u)

// named barrier ids
#define BAR_FULL0 1
#define BAR_FULL1 2
#define BAR_EMPTY0 3
#define BAR_EMPTY1 4
#define BAR_PROD 5
#define BAR_CONS 6

__global__ __launch_bounds__(256, 1) void k_attn(const int* __restrict__ adj) {
    extern __shared__ uint32_t sm[];
    uint32_t smbase = smem_u32(sm);
    uint32_t mbA0 = smbase + MB_OFF * 4u;
    uint32_t mbA1 = mbA0 + 8u;
    uint32_t mbB0 = mbA0 + 16u;
    uint32_t mbB1 = mbA0 + 24u;

    int t = threadIdx.x;
    int w = t >> 5, lane = t & 31;
    int rb = (int)blockIdx.x >> 1, jh = (int)blockIdx.x & 1;
    int i0 = rb * 128, jbase = jh * JW;

    if (t == 0) {
        mbar_init(mbA0, 1);
        mbar_init(mbA1, 1);
        mbar_init(mbB0, 1);
        mbar_init(mbB1, 1);
    }
    __syncthreads();

    if (t >= 128) {
        // ================= PRODUCER (warps 4-7) =================
        int r = t - 128;  // row 0..127
        // prologue: adj+colf for tiles 0,1
#pragma unroll
        for (int pb = 0; pb < 2; pb++) {
            int jc = jbase + pb * 64;
            uint32_t mb = pb ? mbA1 : mbA0;
            if (r == 0) {
                mbar_expect(mb, ADJ_TX);
                bulk_g2s(smbase + (uint32_t)(CF_OFF + pb * 256) * 4u, g_colf + jc, 1024u, mb);
            }
            bulk_g2s(smbase + (uint32_t)(ADJ_OFF + pb * ABUF + r * SAS) * 4u,
                     adj + (size_t)(i0 + r) * NN + jc, 256u, mb);
        }

        float si = g_ssrc[i0 + r];
        float Gi = g_G[i0 + r];
        float nsi = -si;
        float rsum = 0.f;
        int parA[2] = {0, 0};

        for (int tt = 0; tt < NT; tt++) {
            int b = tt & 1;
            mbar_wait(b ? mbA1 : mbA0, parA[b]);
            parA[b] ^= 1;
            if (tt >= 2) bar_sync(b ? BAR_EMPTY1 : BAR_EMPTY0, 256);  // P[b] free

            // build full P row r (64 cols) into P[b]
            const int4* adjS = (const int4*)(sm + ADJ_OFF + b * ABUF + r * SAS);
            const float4* colfS = (const float4*)(sm + CF_OFF + b * 256);
            uint64_t* pDhi = (uint64_t*)(sm + b * PBUF) + (size_t)r * (SPS / 2);
            uint64_t* pDlo = (uint64_t*)(sm + b * PBUF + PLO) + (size_t)r * (SPS / 2);
#pragma unroll 4
            for (int u = 0; u < 16; u++) {
                int4 av = adjS[u];
                int l = u * 4;
                float4 c0 = colfS[l + 0], c1 = colfS[l + 1], c2v = colfS[l + 2], c3 = colfS[l + 3];
                float p0 = (av.x > 0) ? ((c0.z >= nsi) ? Gi * c0.x : c0.y) : 0.f;
                float p1 = (av.y > 0) ? ((c1.z >= nsi) ? Gi * c1.x : c1.y) : 0.f;
                float p2 = (av.z > 0) ? ((c2v.z >= nsi) ? Gi * c2v.x : c2v.y) : 0.f;
                float p3 = (av.w > 0) ? ((c3.z >= nsi) ? Gi * c3.x : c3.y) : 0.f;
                rsum += (p0 + p1) + (p2 + p3);
                uint32_t h01, h23, l01, l23;
                asm("cvt.rn.bf16x2.f32 %0, %1, %2;" : "=r"(h01) : "f"(p1), "f"(p0));
                asm("cvt.rn.bf16x2.f32 %0, %1, %2;" : "=r"(h23) : "f"(p3), "f"(p2));
                float q0 = p0 - __uint_as_float(h01 << 16);
                float q1 = p1 - __uint_as_float(h01 & 0xffff0000u);
                float q2 = p2 - __uint_as_float(h23 << 16);
                float q3 = p3 - __uint_as_float(h23 & 0xffff0000u);
                asm("cvt.rn.bf16x2.f32 %0, %1, %2;" : "=r"(l01) : "f"(q1), "f"(q0));
                asm("cvt.rn.bf16x2.f32 %0, %1, %2;" : "=r"(l23) : "f"(q3), "f"(q2));
                pDhi[u] = (uint64_t)h01 | ((uint64_t)h23 << 32);
                pDlo[u] = (uint64_t)l01 | ((uint64_t)l23 << 32);
            }

            bar_sync(BAR_PROD, 128);  // all producers done reading adj[b]
            if (tt + 2 < NT) {
                int jc = jbase + (tt + 2) * 64;
                uint32_t mb = b ? mbA1 : mbA0;
                if (r == 0) {
                    mbar_expect(mb, ADJ_TX);
                    bulk_g2s(smbase + (uint32_t)(CF_OFF + b * 256) * 4u, g_colf + jc, 1024u, mb);
                }
                bulk_g2s(smbase + (uint32_t)(ADJ_OFF + b * ABUF + r * SAS) * 4u,
                         adj + (size_t)(i0 + r) * NN + jc, 256u, mb);
            }
            bar_arrive(b ? BAR_FULL1 : BAR_FULL0, 256);  // P[b] ready
        }
        g_psum[(size_t)jh * NN + i0 + r] = rsum;
    } else {
        // ================= CONSUMER (warps 0-3) =================
        // prologue: B for tiles 0,1
#pragma unroll
        for (int pb = 0; pb < 2; pb++) {
            int jc = jbase + pb * 64;
            uint32_t mb = pb ? mbB1 : mbB0;
            if (t == 0) mbar_expect(mb, B_TX);
            int f = t & 63;
            uint32_t dst = smbase + (uint32_t)(B_OFF + pb * BBUF + ((t < 64) ? 0 : BLO) + f * SPS) * 4u;
            const void* src = (t < 64) ? (const void*)(g_HThi + (size_t)f * NN + jc)
                                       : (const void*)(g_HTlo + (size_t)f * NN + jc);
            bulk_g2s(dst, src, 128u, mb);
        }

        int cw = w;  // 0..3 -> rows cw*32
        int g = lane >> 2, tg = lane & 3;
        int a_r = ((lane >> 3) & 1) * 8 + (lane & 7);
        uint32_t a_cb = (uint32_t)(lane >> 4) * 16u;
        int b_r = (lane >> 4) * 8 + (lane & 7);
        uint32_t b_cb = (uint32_t)((lane >> 3) & 1) * 16u;
        uint32_t aBase = smbase + (uint32_t)((cw * 32 + a_r) * SPS) * 4u + a_cb;
        uint32_t bBase = smbase + (uint32_t)(B_OFF + b_r * SPS) * 4u + b_cb;
        const uint32_t RS16 = 16u * SPS * 4u;

        float acc[2][8][4];
#pragma unroll
        for (int mi = 0; mi < 2; mi++)
#pragma unroll
            for (int ni = 0; ni < 8; ni++)
#pragma unroll
                for (int q = 0; q < 4; q++) acc[mi][ni][q] = 0.f;

        int parB[2] = {0, 0};

        for (int tt = 0; tt < NT; tt++) {
            int b = tt & 1;
            bar_sync(b ? BAR_FULL1 : BAR_FULL0, 256);  // P[b] ready
            mbar_wait(b ? mbB1 : mbB0, parB[b]);
            parB[b] ^= 1;

            uint32_t aP = aBase + (uint32_t)(b * PBUF) * 4u;
            uint32_t aL = aP + (uint32_t)PLO * 4u;
            uint32_t bH = bBase + (uint32_t)(b * BBUF) * 4u;
            uint32_t bL = bH + (uint32_t)BLO * 4u;

#pragma unroll
            for (int kk = 0; kk < 4; kk++) {
                uint32_t kb = (uint32_t)kk * 32u;
                uint32_t AH0[4], AH1[4], AL0[4], AL1[4];
                uint32_t BH[4][4], BL[4][4];
                ldsm4(AH0, aP + kb);
                ldsm4(AH1, aP + RS16 + kb);
                ldsm4(AL0, aL + kb);
                ldsm4(AL1, aL + RS16 + kb);
#pragma unroll
                for (int nb = 0; nb < 4; nb++) {
                    ldsm4(BH[nb], bH + nb * RS16 + kb);
                    ldsm4(BL[nb], bL + nb * RS16 + kb);
                }
#pragma unroll
                for (int nb = 0; nb < 4; nb++) {
                    // hi*hi
                    mma_bf16(acc[0][2 * nb + 0], AH0, BH[nb][0], BH[nb][1]);
                    mma_bf16(acc[0][2 * nb + 1], AH0, BH[nb][2], BH[nb][3]);
                    mma_bf16(acc[1][2 * nb + 0], AH1, BH[nb][0], BH[nb][1]);
                    mma_bf16(acc[1][2 * nb + 1], AH1, BH[nb][2], BH[nb][3]);
                    // hi*lo
                    mma_bf16(acc[0][2 * nb + 0], AH0, BL[nb][0], BL[nb][1]);
                    mma_bf16(acc[0][2 * nb + 1], AH0, BL[nb][2], BL[nb][3]);
                    mma_bf16(acc[1][2 * nb + 0], AH1, BL[nb][0], BL[nb][1]);
                    mma_bf16(acc[1][2 * nb + 1], AH1, BL[nb][2], BL[nb][3]);
                    // lo*hi
                    mma_bf16(acc[0][2 * nb + 0], AL0, BH[nb][0], BH[nb][1]);
                    mma_bf16(acc[0][2 * nb + 1], AL0, BH[nb][2], BH[nb][3]);
                    mma_bf16(acc[1][2 * nb + 0], AL1, BH[nb][0], BH[nb][1]);
                    mma_bf16(acc[1][2 * nb + 1], AL1, BH[nb][2], BH[nb][3]);
                }
            }

            bar_sync(BAR_CONS, 128);  // all consumers done with P[b], B[b]
            if (tt + 2 < NT) {
                int jc = jbase + (tt + 2) * 64;
                uint32_t mb = b ? mbB1 : mbB0;
                if (t == 0) mbar_expect(mb, B_TX);
                int f = t & 63;
                uint32_t dst = smbase + (uint32_t)(B_OFF + b * BBUF + ((t < 64) ? 0 : BLO) + f * SPS) * 4u;
                const void* src = (t < 64) ? (const void*)(g_HThi + (size_t)f * NN + jc)
                                           : (const void*)(g_HTlo + (size_t)f * NN + jc);
                bulk_g2s(dst, src, 128u, mb);
            }
            bar_arrive(b ? BAR_EMPTY1 : BAR_EMPTY0, 256);  // P[b] free
        }

        // epilogue: store partial numerators
#pragma unroll
        for (int mi = 0; mi < 2; mi++) {
            int r0 = i0 + cw * 32 + mi * 16 + g;
#pragma unroll
            for (int ni = 0; ni < 8; ni++) {
                int c = ni * 8 + tg * 2;
                *(float2*)(g_part + ((size_t)jh * NN + r0) * FOUT + c) =
                    make_float2(acc[mi][ni][0], acc[mi][ni][1]);
                *(float2*)(g_part + ((size_t)jh * NN + r0 + 8) * FOUT + c) =
                    make_float2(acc[mi][ni][2], acc[mi][ni][3]);
            }
        }
    }
}

// ---------------- Kernel C: combine halves + normalize + ELU ----------------
__global__ __launch_bounds__(256) void k_combine(float* __restrict__ out) {
    int v = blockIdx.x * blockDim.x + threadIdx.x;  // float4 index
    int row = v >> 4;
    float s = g_psum[row] + g_psum[NN + row];
    float inv = 1.0f / s;
    float4 a0 = ((const float4*)g_part)[v];
    float4 a1 = ((const float4*)(g_part + (size_t)NN * FOUT))[v];
    float4 o;
    o.x = (a0.x + a1.x) * inv;
    o.y = (a0.y + a1.y) * inv;
    o.z = (a0.z + a1.z) * inv;
    o.w = (a0.w + a1.w) * inv;
    o.x = (o.x > 0.f) ? o.x : expm1f(o.x);
    o.y = (o.y > 0.f) ? o.y : expm1f(o.y);
    o.z = (o.z > 0.f) ? o.z : expm1f(o.z);
    o.w = (o.w > 0.f) ? o.w : expm1f(o.w);
    ((float4*)out)[v] = o;
}

extern "C" void kernel_launch(void* const* d_in, const int* in_sizes, int n_in,
                              void* d_out, int out_size) {
    const float* X = (const float*)d_in[0];   // 8192x512
    const int* adj = (const int*)d_in[1];     // 8192x8192
    const float* W = (const float*)d_in[2];   // 512x64
    const float* a = (const float*)d_in[3];   // 128x1
    float* out = (float*)d_out;               // 8192x64

    float* H;
    cudaGetSymbolAddress((void**)&H, g_h);

    static int inited = 0;
    if (!inited) {
        cudaFuncSetAttribute(k_attn, cudaFuncAttributeMaxDynamicSharedMemorySize,
                             SMEM_U32 * 4);
        inited = 1;
    }

    k_gemm_h<<<NN / 64, 256>>>(X, W, H);
    k_scores<<<NN / 256, 256>>>(H, a);
    k_transpose<<<NN / 64, 256>>>();
    k_attn<<<128, 256, SMEM_U32 * 4>>>(adj);
    k_combine<<<(NN * FOUT / 4) / 256, 256>>>(out);
}

// round 15
// speedup vs baseline: 1.1883x; 1.1883x over previous
#include <cuda_runtime.h>
#include <cuda_bf16.h>
#include <cstdint>

#define NN 8192
#define FIN 512
#define FOUT 64
#define JW 4096       // cols per CTA (j halves)
#define NT (JW / 128) // 32 tiles of 128 cols

// ---------------- scratch globals (no allocations allowed) ----------------
__device__ float g_h[NN * FOUT];
__device__ float g_ssrc[NN];
__device__ float g_G[NN];                    // exp(0.8 * s_src)
__device__ float4 g_colf[NN];                // {F=exp(sd), F02=exp(0.2 sd), sd, 0}
__device__ __nv_bfloat16 g_HThi[FOUT * NN];  // H^T hi bf16, tile-blocked [jblk][f][c] swizzled
__device__ __nv_bfloat16 g_HTlo[FOUT * NN];  // H^T lo bf16, same layout
__device__ uint4 g_adjbits[NN * 64];         // 8 MB: bit q of comp k at group g = adj[row][g*128+4k+q]
__device__ float g_part[2 * NN * FOUT];      // partial numerators per j-half
__device__ float g_psum[2 * NN];             // partial row sums per j-half

__device__ __forceinline__ uint32_t smem_u32(const void* p) {
    uint32_t a;
    asm("{ .reg .u64 t; cvta.to.shared.u64 t, %1; cvt.u32.u64 %0, t; }" : "=r"(a) : "l"(p));
    return a;
}
__device__ __forceinline__ void ldsm4(uint32_t* r, uint32_t addr) {
    asm volatile("ldmatrix.sync.aligned.m8n8.x4.shared.b16 {%0,%1,%2,%3}, [%4];"
                 : "=r"(r[0]), "=r"(r[1]), "=r"(r[2]), "=r"(r[3]) : "r"(addr));
}
__device__ __forceinline__ void mma_bf16(float* c, const uint32_t* a, uint32_t b0, uint32_t b1) {
    asm volatile(
        "mma.sync.aligned.m16n8k16.row.col.f32.bf16.bf16.f32 "
        "{%0,%1,%2,%3}, {%4,%5,%6,%7}, {%8,%9}, {%0,%1,%2,%3};"
        : "+f"(c[0]), "+f"(c[1]), "+f"(c[2]), "+f"(c[3])
        : "r"(a[0]), "r"(a[1]), "r"(a[2]), "r"(a[3]), "r"(b0), "r"(b1));
}
__device__ __forceinline__ void mbar_init(uint32_t a, uint32_t c) {
    asm volatile("mbarrier.init.shared.b64 [%0], %1;" :: "r"(a), "r"(c) : "memory");
}
__device__ __forceinline__ void mbar_expect(uint32_t a, uint32_t tx) {
    asm volatile("mbarrier.arrive.expect_tx.shared.b64 _, [%0], %1;" :: "r"(a), "r"(tx) : "memory");
}
__device__ __forceinline__ void mbar_wait(uint32_t a, uint32_t par) {
    asm volatile(
        "{\n\t.reg .pred P1;\n\t"
        "WL_%=:\n\t"
        "mbarrier.try_wait.parity.acquire.cta.shared::cta.b64 P1, [%0], %1, 0x989680;\n\t"
        "@P1 bra.uni WD_%=;\n\t"
        "bra.uni WL_%=;\n\t"
        "WD_%=:\n\t}"
        :: "r"(a), "r"(par) : "memory");
}
__device__ __forceinline__ void bulk_g2s(uint32_t dst, const void* src, uint32_t bytes, uint32_t mbar) {
    asm volatile(
        "cp.async.bulk.shared::cta.global.mbarrier::complete_tx::bytes [%0], [%1], %2, [%3];"
        :: "r"(dst), "l"(src), "r"(bytes), "r"(mbar) : "memory");
}
__device__ __forceinline__ void bar_sync(int id, int cnt) {
    asm volatile("bar.sync %0, %1;" :: "r"(id), "r"(cnt) : "memory");
}
__device__ __forceinline__ void bar_arrive(int id, int cnt) {
    asm volatile("bar.arrive %0, %1;" :: "r"(id), "r"(cnt) : "memory");
}

// ---------------- Kernel P: pack adj to bits ----------------
// group g = 128 consecutive cols of one row. out[g] = uint4; comp q, bit k <-> col 128g_local.. :
// col = 4*k + q within group (lane k reads int4 of cols 4k..4k+3).
__global__ __launch_bounds__(256) void k_pack(const int4* __restrict__ adj4, uint4* __restrict__ out) {
    int lane = threadIdx.x & 31;
    int wid = (blockIdx.x * blockDim.x + threadIdx.x) >> 5;
    int nwarp = (gridDim.x * blockDim.x) >> 5;
    for (int gidx = wid; gidx < NN * 64; gidx += nwarp) {
        int4 v = adj4[(size_t)gidx * 32 + lane];
        uint32_t b0 = __ballot_sync(0xffffffffu, v.x > 0);
        uint32_t b1 = __ballot_sync(0xffffffffu, v.y > 0);
        uint32_t b2 = __ballot_sync(0xffffffffu, v.z > 0);
        uint32_t b3 = __ballot_sync(0xffffffffu, v.w > 0);
        if (lane == 0) out[gidx] = make_uint4(b0, b1, b2, b3);
    }
}

// ---------------- Kernel A: h = X @ W ----------------
__global__ __launch_bounds__(256) void k_gemm_h(const float* __restrict__ X,
                                                const float* __restrict__ W,
                                                float* __restrict__ H) {
    __shared__ float sA[32][65];
    __shared__ float sB[32][68];
    int t = threadIdx.x;
    int m0 = blockIdx.x * 64;
    int tr = t >> 4, tc = t & 15;
    float acc[4][4];
#pragma unroll
    for (int i = 0; i < 4; i++)
#pragma unroll
        for (int j = 0; j < 4; j++) acc[i][j] = 0.f;

    float rA[8], rB[8];
#pragma unroll
    for (int u = 0; u < 8; u++) {
        int g = u * 256 + t;
        int m = g >> 5, k = g & 31;
        rA[u] = X[(m0 + m) * FIN + k];
    }
#pragma unroll
    for (int u = 0; u < 8; u++) {
        int g = u * 256 + t;
        int k = g >> 6, n = g & 63;
        rB[u] = W[k * FOUT + n];
    }

    for (int kc = 0; kc < 16; kc++) {
        __syncthreads();
#pragma unroll
        for (int u = 0; u < 8; u++) {
            int g = u * 256 + t;
            int m = g >> 5, k = g & 31;
            sA[k][m] = rA[u];
        }
#pragma unroll
        for (int u = 0; u < 8; u++) {
            int g = u * 256 + t;
            int k = g >> 6, n = g & 63;
            sB[k][n] = rB[u];
        }
        __syncthreads();
        if (kc + 1 < 16) {
            int k0 = (kc + 1) * 32;
#pragma unroll
            for (int u = 0; u < 8; u++) {
                int g = u * 256 + t;
                int m = g >> 5, k = g & 31;
                rA[u] = X[(m0 + m) * FIN + k0 + k];
            }
#pragma unroll
            for (int u = 0; u < 8; u++) {
                int g = u * 256 + t;
                int k = g >> 6, n = g & 63;
                rB[u] = W[(k0 + k) * FOUT + n];
            }
        }
#pragma unroll
        for (int k = 0; k < 32; k++) {
            float a[4], b[4];
#pragma unroll
            for (int i = 0; i < 4; i++) a[i] = sA[k][tr + 16 * i];
#pragma unroll
            for (int j = 0; j < 4; j++) b[j] = sB[k][tc + 16 * j];
#pragma unroll
            for (int i = 0; i < 4; i++)
#pragma unroll
                for (int j = 0; j < 4; j++) acc[i][j] += a[i] * b[j];
        }
    }
#pragma unroll
    for (int i = 0; i < 4; i++)
#pragma unroll
        for (int j = 0; j < 4; j++)
            H[(m0 + tr + 16 * i) * FOUT + tc + 16 * j] = acc[i][j];
}

// ---------------- Kernel A2: scores + exp factors ----------------
__global__ __launch_bounds__(256) void k_scores(const float* __restrict__ H,
                                                const float* __restrict__ a) {
    int i = blockIdx.x * blockDim.x + threadIdx.x;
    const float4* hr = (const float4*)(H + i * FOUT);
    const float4* av = (const float4*)a;
    float ss = 0.f, sd = 0.f;
#pragma unroll
    for (int f = 0; f < 16; f++) {
        float4 h = hr[f];
        float4 as = av[f];
        float4 ad = av[16 + f];
        ss += h.x * as.x + h.y * as.y + h.z * as.z + h.w * as.w;
        sd += h.x * ad.x + h.y * ad.y + h.z * ad.z + h.w * ad.w;
    }
    g_ssrc[i] = ss;
    g_G[i] = expf(0.8f * ss);
    g_colf[i] = make_float4(expf(sd), expf(0.2f * sd), sd, 0.f);
}

// ---------------- Kernel A3: transpose H -> blocked swizzled HT hi/lo ----------------
// g_HThi layout: [jblk (128 nodes)][f 0..63][c 0..127], byte off within 16KB tile:
//   f*256 + ((c*2) ^ ((f&7)<<4))
__global__ __launch_bounds__(256) void k_transpose() {
    __shared__ float tile[64][65];
    int t = threadIdx.x;
    int i0 = blockIdx.x * 64;
#pragma unroll
    for (int u = 0; u < 16; u++) {
        int idx = u * 256 + t;
        int r = idx >> 6, c = idx & 63;
        tile[r][c] = g_h[(i0 + r) * FOUT + c];
    }
    __syncthreads();
#pragma unroll
    for (int u = 0; u < 16; u++) {
        int idx = u * 256 + t;
        int f = idx >> 6, i = idx & 63;
        float v = tile[i][f];
        __nv_bfloat16 hb = __float2bfloat16(v);
        float hv = __bfloat162float(hb);
        __nv_bfloat16 lb = __float2bfloat16(v - hv);
        int node = i0 + i;
        int jblk = node >> 7;
        uint32_t c = (uint32_t)(node & 127);
        uint32_t off = (uint32_t)f * 256u + ((c * 2u) ^ (((uint32_t)f & 7u) << 4));
        *(__nv_bfloat16*)((char*)g_HThi + (size_t)jblk * 16384 + off) = hb;
        *(__nv_bfloat16*)((char*)g_HTlo + (size_t)jblk * 16384 + off) = lb;
    }
}

// ---------------- Kernel B: warp-specialized HMMA attention, bit adj ----------------
// smem (u32 offsets):
//   P[b]: hi at b*17408, lo at b*17408+8704  (128 rows x 68 u32, BK=128)
//   B[b]: 34816 + b*8192; hi +0 (4096), lo +4096  ([64 f][256B] swizzled)
//   colf[b]: 51200 + b*512  (128 float4)
//   mbars: 52224  (A0,A1 colf; B0,B1)
#define SPS 68
#define PBUF 17408
#define PLO 8704
#define B_OFF 34816
#define BBUF 8192
#define CF_OFF 51200
#define MB_OFF 52224
#define SMEM_U32 52232  // 208928 bytes

#define CF_TX 2048u
#define B_TX 32768u

#define BAR_FULL0 1
#define BAR_FULL1 2
#define BAR_EMPTY0 3
#define BAR_EMPTY1 4
#define BAR_PROD 5
#define BAR_CONS 6

__global__ __launch_bounds__(256, 1) void k_attn() {
    extern __shared__ uint32_t sm[];
    uint32_t smbase = smem_u32(sm);
    uint32_t mbA0 = smbase + MB_OFF * 4u;
    uint32_t mbA1 = mbA0 + 8u;
    uint32_t mbB0 = mbA0 + 16u;
    uint32_t mbB1 = mbA0 + 24u;

    int t = threadIdx.x;
    int w = t >> 5, lane = t & 31;
    int rb = (int)blockIdx.x >> 1, jh = (int)blockIdx.x & 1;
    int i0 = rb * 128, jbase = jh * JW;

    if (t == 0) {
        mbar_init(mbA0, 1);
        mbar_init(mbA1, 1);
        mbar_init(mbB0, 1);
        mbar_init(mbB1, 1);
    }
    __syncthreads();

    if (t >= 128) {
        // ================= PRODUCER (warps 4-7): build P from bitmask =================
        int r = t - 128;  // row 0..127
        // prologue: colf for tiles 0,1
        if (r == 0) {
#pragma unroll
            for (int pb = 0; pb < 2; pb++) {
                uint32_t mb = pb ? mbA1 : mbA0;
                mbar_expect(mb, CF_TX);
                bulk_g2s(smbase + (uint32_t)(CF_OFF + pb * 512) * 4u, g_colf + jbase + pb * 128, CF_TX, mb);
            }
        }
        float si = g_ssrc[i0 + r];
        float Gi = g_G[i0 + r];
        float nsi = -si;
        const uint4* mrow = g_adjbits + (size_t)(i0 + r) * 64 + jh * 32;
        uint4 cur = mrow[0];
        int parA[2] = {0, 0};

        for (int tt = 0; tt < NT; tt++) {
            int b = tt & 1;
            uint4 nxt = (tt + 1 < NT) ? mrow[tt + 1] : make_uint4(0, 0, 0, 0);
            mbar_wait(b ? mbA1 : mbA0, parA[b]);
            parA[b] ^= 1;
            if (tt >= 2) bar_sync(b ? BAR_EMPTY1 : BAR_EMPTY0, 256);

            const float4* colfS = (const float4*)(sm + CF_OFF + b * 512);
            uint64_t* pDhi = (uint64_t*)(sm + b * PBUF) + (size_t)r * (SPS / 2);
            uint64_t* pDlo = (uint64_t*)(sm + b * PBUF + PLO) + (size_t)r * (SPS / 2);
#pragma unroll 4
            for (int u = 0; u < 32; u++) {
                float4 c0 = colfS[4 * u + 0], c1 = colfS[4 * u + 1];
                float4 c2v = colfS[4 * u + 2], c3 = colfS[4 * u + 3];
                float t0 = (c0.z >= nsi) ? Gi * c0.x : c0.y;
                float t1 = (c1.z >= nsi) ? Gi * c1.x : c1.y;
                float t2 = (c2v.z >= nsi) ? Gi * c2v.x : c2v.y;
                float t3 = (c3.z >= nsi) ? Gi * c3.x : c3.y;
                float p0 = ((cur.x >> u) & 1u) ? t0 : 0.f;
                float p1 = ((cur.y >> u) & 1u) ? t1 : 0.f;
                float p2 = ((cur.z >> u) & 1u) ? t2 : 0.f;
                float p3 = ((cur.w >> u) & 1u) ? t3 : 0.f;
                uint32_t h01, h23, l01, l23;
                asm("cvt.rn.bf16x2.f32 %0, %1, %2;" : "=r"(h01) : "f"(p1), "f"(p0));
                asm("cvt.rn.bf16x2.f32 %0, %1, %2;" : "=r"(h23) : "f"(p3), "f"(p2));
                float q0 = p0 - __uint_as_float(h01 << 16);
                float q1 = p1 - __uint_as_float(h01 & 0xffff0000u);
                float q2 = p2 - __uint_as_float(h23 << 16);
                float q3 = p3 - __uint_as_float(h23 & 0xffff0000u);
                asm("cvt.rn.bf16x2.f32 %0, %1, %2;" : "=r"(l01) : "f"(q1), "f"(q0));
                asm("cvt.rn.bf16x2.f32 %0, %1, %2;" : "=r"(l23) : "f"(q3), "f"(q2));
                pDhi[u] = (uint64_t)h01 | ((uint64_t)h23 << 32);
                pDlo[u] = (uint64_t)l01 | ((uint64_t)l23 << 32);
            }

            bar_sync(BAR_PROD, 128);  // all producers done reading colf[b]
            if (tt + 2 < NT && r == 0) {
                uint32_t mb = b ? mbA1 : mbA0;
                mbar_expect(mb, CF_TX);
                bulk_g2s(smbase + (uint32_t)(CF_OFF + b * 512) * 4u,
                         g_colf + jbase + (tt + 2) * 128, CF_TX, mb);
            }
            bar_arrive(b ? BAR_FULL1 : BAR_FULL0, 256);  // P[b] ready
            cur = nxt;
        }
    } else {
        // ================= CONSUMER (warps 0-3) =================
        int jblk0 = jbase >> 7;
        // prologue: B for tiles 0,1 (single 16KB op per hi/lo)
        if (t == 0) {
#pragma unroll
            for (int pb = 0; pb < 2; pb++) {
                uint32_t mb = pb ? mbB1 : mbB0;
                mbar_expect(mb, B_TX);
                bulk_g2s(smbase + (uint32_t)(B_OFF + pb * BBUF) * 4u,
                         (const char*)g_HThi + (size_t)(jblk0 + pb) * 16384, 16384u, mb);
                bulk_g2s(smbase + (uint32_t)(B_OFF + pb * BBUF + 4096) * 4u,
                         (const char*)g_HTlo + (size_t)(jblk0 + pb) * 16384, 16384u, mb);
            }
        }

        int cw = w;  // 0..3 -> rows cw*32
        int g = lane >> 2, tg = lane & 3;
        int a_r = ((lane >> 3) & 1) * 8 + (lane & 7);
        uint32_t a_cb = (uint32_t)(lane >> 4) * 16u;
        int b_r = (lane >> 4) * 8 + (lane & 7);
        uint32_t b_cb = (uint32_t)((lane >> 3) & 1) * 16u;
        uint32_t xr = ((uint32_t)b_r & 7u) << 4;

        uint32_t aBase = smbase + (uint32_t)((cw * 32 + a_r) * SPS) * 4u + a_cb;
        uint32_t bRow = smbase + (uint32_t)B_OFF * 4u + (uint32_t)b_r * 256u;
        const uint32_t RS16 = 16u * SPS * 4u;
        const uint32_t ONES = 0x3F803F80u;  // bf16 {1.0, 1.0}

        float acc[2][8][4];
#pragma unroll
        for (int mi = 0; mi < 2; mi++)
#pragma unroll
            for (int ni = 0; ni < 8; ni++)
#pragma unroll
                for (int q = 0; q < 4; q++) acc[mi][ni][q] = 0.f;
        float accS[2][4];
#pragma unroll
        for (int mi = 0; mi < 2; mi++)
#pragma unroll
            for (int q = 0; q < 4; q++) accS[mi][q] = 0.f;

        int parB[2] = {0, 0};

        for (int tt = 0; tt < NT; tt++) {
            int b = tt & 1;
            bar_sync(b ? BAR_FULL1 : BAR_FULL0, 256);  // P[b] ready
            mbar_wait(b ? mbB1 : mbB0, parB[b]);
            parB[b] ^= 1;

            uint32_t aP = aBase + (uint32_t)(b * PBUF) * 4u;
            uint32_t aL = aP + (uint32_t)PLO * 4u;
            uint32_t bH = bRow + (uint32_t)(b * BBUF) * 4u;
            uint32_t bL = bH + 16384u;

#pragma unroll
            for (int kk = 0; kk < 8; kk++) {
                uint32_t kb = (uint32_t)kk * 32u;
                uint32_t kbw = (b_cb + kb) ^ xr;
                uint32_t AH0[4], AH1[4], AL0[4], AL1[4];
                uint32_t BH[4][4], BL[4][4];
                ldsm4(AH0, aP + kb);
                ldsm4(AH1, aP + RS16 + kb);
                ldsm4(AL0, aL + kb);
                ldsm4(AL1, aL + RS16 + kb);
#pragma unroll
                for (int nb = 0; nb < 4; nb++) {
                    ldsm4(BH[nb], bH + (uint32_t)nb * 4096u + kbw);
                    ldsm4(BL[nb], bL + (uint32_t)nb * 4096u + kbw);
                }
#pragma unroll
                for (int nb = 0; nb < 4; nb++) {
                    // hi*hi
                    mma_bf16(acc[0][2 * nb + 0], AH0, BH[nb][0], BH[nb][1]);
                    mma_bf16(acc[0][2 * nb + 1], AH0, BH[nb][2], BH[nb][3]);
                    mma_bf16(acc[1][2 * nb + 0], AH1, BH[nb][0], BH[nb][1]);
                    mma_bf16(acc[1][2 * nb + 1], AH1, BH[nb][2], BH[nb][3]);
                    // hi*lo
                    mma_bf16(acc[0][2 * nb + 0], AH0, BL[nb][0], BL[nb][1]);
                    mma_bf16(acc[0][2 * nb + 1], AH0, BL[nb][2], BL[nb][3]);
                    mma_bf16(acc[1][2 * nb + 0], AH1, BL[nb][0], BL[nb][1]);
                    mma_bf16(acc[1][2 * nb + 1], AH1, BL[nb][2], BL[nb][3]);
                    // lo*hi
                    mma_bf16(acc[0][2 * nb + 0], AL0, BH[nb][0], BH[nb][1]);
                    mma_bf16(acc[0][2 * nb + 1], AL0, BH[nb][2], BH[nb][3]);
                    mma_bf16(acc[1][2 * nb + 0], AL1, BH[nb][0], BH[nb][1]);
                    mma_bf16(acc[1][2 * nb + 1], AL1, BH[nb][2], BH[nb][3]);
                }
                // row sums via ones-column MMA (P hi + P lo)
                mma_bf16(accS[0], AH0, ONES, ONES);
                mma_bf16(accS[0], AL0, ONES, ONES);
                mma_bf16(accS[1], AH1, ONES, ONES);
                mma_bf16(accS[1], AL1, ONES, ONES);
            }

            bar_sync(BAR_CONS, 128);  // all consumers done with P[b], B[b]
            if (tt + 2 < NT && t == 0) {
                uint32_t mb = b ? mbB1 : mbB0;
                mbar_expect(mb, B_TX);
                bulk_g2s(smbase + (uint32_t)(B_OFF + b * BBUF) * 4u,
                         (const char*)g_HThi + (size_t)(jblk0 + tt + 2) * 16384, 16384u, mb);
                bulk_g2s(smbase + (uint32_t)(B_OFF + b * BBUF + 4096) * 4u,
                         (const char*)g_HTlo + (size_t)(jblk0 + tt + 2) * 16384, 16384u, mb);
            }
            bar_arrive(b ? BAR_EMPTY1 : BAR_EMPTY0, 256);  // P[b], B[b] free
        }

        // epilogue: partial numerators
#pragma unroll
        for (int mi = 0; mi < 2; mi++) {
            int r0 = i0 + cw * 32 + mi * 16 + g;
#pragma unroll
            for (int ni = 0; ni < 8; ni++) {
                int c = ni * 8 + tg * 2;
                *(float2*)(g_part + ((size_t)jh * NN + r0) * FOUT + c) =
                    make_float2(acc[mi][ni][0], acc[mi][ni][1]);
                *(float2*)(g_part + ((size_t)jh * NN + r0 + 8) * FOUT + c) =
                    make_float2(acc[mi][ni][2], acc[mi][ni][3]);
            }
        }
        // row sums (cols identical across tg; tg==0 lanes write)
        if (tg == 0) {
            size_t base = (size_t)jh * NN + i0 + cw * 32 + g;
            g_psum[base] = accS[0][0];
            g_psum[base + 8] = accS[0][2];
            g_psum[base + 16] = accS[1][0];
            g_psum[base + 24] = accS[1][2];
        }
    }
}

// ---------------- Kernel C: combine halves + normalize + ELU ----------------
__global__ __launch_bounds__(256) void k_combine(float* __restrict__ out) {
    int v = blockIdx.x * blockDim.x + threadIdx.x;  // float4 index
    int row = v >> 4;
    float s = g_psum[row] + g_psum[NN + row];
    float inv = 1.0f / s;
    float4 a0 = ((const float4*)g_part)[v];
    float4 a1 = ((const float4*)(g_part + (size_t)NN * FOUT))[v];
    float4 o;
    o.x = (a0.x + a1.x) * inv;
    o.y = (a0.y + a1.y) * inv;
    o.z = (a0.z + a1.z) * inv;
    o.w = (a0.w + a1.w) * inv;
    o.x = (o.x > 0.f) ? o.x : expm1f(o.x);
    o.y = (o.y > 0.f) ? o.y : expm1f(o.y);
    o.z = (o.z > 0.f) ? o.z : expm1f(o.z);
    o.w = (o.w > 0.f) ? o.w : expm1f(o.w);
    ((float4*)out)[v] = o;
}

extern "C" void kernel_launch(void* const* d_in, const int* in_sizes, int n_in,
                              void* d_out, int out_size) {
    const float* X = (const float*)d_in[0];   // 8192x512
    const int* adj = (const int*)d_in[1];     // 8192x8192
    const float* W = (const float*)d_in[2];   // 512x64
    const float* a = (const float*)d_in[3];   // 128x1
    float* out = (float*)d_out;               // 8192x64

    float* H;
    cudaGetSymbolAddress((void**)&H, g_h);
    uint4* bits;
    cudaGetSymbolAddress((void**)&bits, g_adjbits);

    static int inited = 0;
    if (!inited) {
        cudaFuncSetAttribute(k_attn, cudaFuncAttributeMaxDynamicSharedMemorySize,
                             SMEM_U32 * 4);
        inited = 1;
    }

    k_pack<<<1024, 256>>>((const int4*)adj, bits);
    k_gemm_h<<<NN / 64, 256>>>(X, W, H);
    k_scores<<<NN / 256, 256>>>(H, a);
    k_transpose<<<NN / 64, 256>>>();
    k_attn<<<128, 256, SMEM_U32 * 4>>>();
    k_combine<<<(NN * FOUT / 4) / 256, 256>>>(out);
}